// round 10
// baseline (speedup 1.0000x reference)
#include <cuda_runtime.h>
#include <cuda_fp16.h>
#include <cuda_fp8.h>
#include <cstdint>

#define B_ 4
#define D_ 1024
#define S_ 2048

// ---------------------------------------------------------------------------
// Scratch (static __device__ arrays; allocation-free)
// Each tensor X has 3 forms: Xh = fp16(X), X8 = e4m3(X), Xl8 = e4m3((X-Xh)*2048)
// ---------------------------------------------------------------------------
__device__ __half   g_xTh[(size_t)B_ * S_ * D_];
__device__ uint8_t  g_xT8 [(size_t)B_ * S_ * D_];
__device__ uint8_t  g_xTl8[(size_t)B_ * S_ * D_];
__device__ __half   g_Wqh[(size_t)D_ * D_];
__device__ uint8_t  g_Wq8[(size_t)D_ * D_], g_Wql8[(size_t)D_ * D_];
__device__ __half   g_Wkh[(size_t)D_ * D_];
__device__ uint8_t  g_Wk8[(size_t)D_ * D_], g_Wkl8[(size_t)D_ * D_];
__device__ __half   g_Wvh[(size_t)D_ * D_];
__device__ uint8_t  g_Wv8[(size_t)D_ * D_], g_Wvl8[(size_t)D_ * D_];
__device__ __half   g_Qh[(size_t)B_ * S_ * D_];
__device__ uint8_t  g_Q8[(size_t)B_ * S_ * D_], g_Ql8[(size_t)B_ * S_ * D_];
__device__ __half   g_Kh[(size_t)B_ * S_ * D_];
__device__ uint8_t  g_K8[(size_t)B_ * S_ * D_], g_Kl8[(size_t)B_ * S_ * D_];
__device__ __half   g_Vh[(size_t)B_ * D_ * S_];
__device__ uint8_t  g_V8[(size_t)B_ * D_ * S_], g_Vl8[(size_t)B_ * D_ * S_];
__device__ float    g_S [(size_t)B_ * S_ * S_];
__device__ __half   g_Ph[(size_t)B_ * S_ * S_];
__device__ uint8_t  g_P8[(size_t)B_ * S_ * S_], g_Pl8[(size_t)B_ * S_ * S_];

// ---------------------------------------------------------------------------
// PTX helpers
// ---------------------------------------------------------------------------
__device__ __forceinline__ uint32_t smem_to_u32(const void* p) {
    uint32_t a;
    asm("{ .reg .u64 t; cvta.to.shared.u64 t, %1; cvt.u32.u64 %0, t; }"
        : "=r"(a) : "l"(p));
    return a;
}

#define CP_ASYNC16(dst_u32, src_ptr) \
    asm volatile("cp.async.cg.shared.global [%0], [%1], 16;" \
                 :: "r"(dst_u32), "l"(src_ptr) : "memory")

#define CP_COMMIT() asm volatile("cp.async.commit_group;" ::: "memory")

#define CP_WAIT(N) asm volatile("cp.async.wait_group %0;" :: "n"(N) : "memory")

#define LDSM4(R, addr) \
    asm volatile("ldmatrix.sync.aligned.m8n8.x4.shared.b16 {%0,%1,%2,%3}, [%4];" \
                 : "=r"((R)[0]), "=r"((R)[1]), "=r"((R)[2]), "=r"((R)[3]) \
                 : "r"(addr))

#define MMA16816(D, A, Bf) \
    asm("mma.sync.aligned.m16n8k16.row.col.f32.f16.f16.f32 " \
        "{%0,%1,%2,%3}, {%4,%5,%6,%7}, {%8,%9}, {%0,%1,%2,%3};" \
        : "+f"((D)[0]), "+f"((D)[1]), "+f"((D)[2]), "+f"((D)[3]) \
        : "r"((A)[0]), "r"((A)[1]), "r"((A)[2]), "r"((A)[3]), \
          "r"((Bf)[0]), "r"((Bf)[1]))

#define MMAF8(D, A, Bf) \
    asm("mma.sync.aligned.m16n8k32.row.col.f32.e4m3.e4m3.f32 " \
        "{%0,%1,%2,%3}, {%4,%5,%6,%7}, {%8,%9}, {%0,%1,%2,%3};" \
        : "+f"((D)[0]), "+f"((D)[1]), "+f"((D)[2]), "+f"((D)[3]) \
        : "r"((A)[0]), "r"((A)[1]), "r"((A)[2]), "r"((A)[3]), \
          "r"((Bf)[0]), "r"((Bf)[1]))

__device__ __forceinline__ uint8_t to_e4m3(float v) {
    return (uint8_t)__nv_cvt_float_to_fp8(v, __NV_SATFINITE, __NV_E4M3);
}

#define RSCALE 2048.0f
#define INV_RSCALE (1.0f / 2048.0f)

// Make the 3 forms of a value: fp16 hi, e4m3(v), e4m3(residual*2048)
__device__ __forceinline__ void split3(float v, __half& h,
                                       uint8_t& f8, uint8_t& fl8) {
    h = __float2half_rn(v);
    f8 = to_e4m3(v);
    fl8 = to_e4m3((v - __half2float(h)) * RSCALE);
}

// ---------------------------------------------------------------------------
// GEMM: D[m,n] = sum_k A[m,k]*B[n,k]
//   acc_hi += Ah(fp16) * Bh(fp16)                 [2x m16n8k16 per k32]
//   acc_lo += A8 * Bl8(x2048) + Al8(x2048) * B8   [2x m16n8k32 e4m3 per k32]
//   v = acc_hi + acc_lo/2048
// MODE 0: h/8/l8 out, +bias[n]; MODE 1: h/8/l8 out, +bias[m];
// MODE 2: fp32 out * 1/32;      MODE 3: fp32 out
// CTA 128x64, 8 warps (4m x 2n), warp tile 32x32. 3-stage cp.async.
// fp16 pitch 80B; fp8 pitch 48B (both conflict-free for ldmatrix).
// ---------------------------------------------------------------------------
#define SM_AH  0
#define SM_BH  10240
#define SM_A8  15360
#define SM_AL8 21504
#define SM_B8  27648
#define SM_BL8 30720
#define STAGE_BYTES 33792
#define NSTAGE 3

template <int KEL, int MODE>
__global__ __launch_bounds__(256, 2) void tc_gemm(
    const __half* __restrict__ Ah, const uint8_t* __restrict__ A8,
    const uint8_t* __restrict__ Al8, size_t sA,
    const __half* __restrict__ Bh, const uint8_t* __restrict__ B8,
    const uint8_t* __restrict__ Bl8, size_t sB,
    const float* __restrict__ bias,
    float* __restrict__ outF,
    __half* __restrict__ outH, uint8_t* __restrict__ out8,
    uint8_t* __restrict__ outL8,
    size_t sO, int ldo)
{
    extern __shared__ char smem[];
    const uint32_t smem_base = smem_to_u32(smem);
    const int tid = threadIdx.x;
    const int wid = tid >> 5;
    const int lid = tid & 31;
    const int wm = wid >> 1;          // 0..3 (M)
    const int wn = wid & 1;           // 0..1 (N)
    const int b = blockIdx.z;
    const int m0 = blockIdx.y * 128;
    const int n0 = blockIdx.x * 64;

    Ah += (size_t)b * sA; A8 += (size_t)b * sA; Al8 += (size_t)b * sA;
    Bh += (size_t)b * sB; B8 += (size_t)b * sB; Bl8 += (size_t)b * sB;

    float acc_hi[2][4][4], acc_lo[2][4][4];
    #pragma unroll
    for (int i = 0; i < 2; ++i)
        #pragma unroll
        for (int j = 0; j < 4; ++j)
            #pragma unroll
            for (int k = 0; k < 4; ++k) { acc_hi[i][j][k] = 0.f; acc_lo[i][j][k] = 0.f; }

    constexpr int NC = KEL / 32;

    // ---- async load of one k32 chunk into stage (c % 3) ----
    auto load_chunk = [&](int c) {
        const int koff = c * 32;
        const uint32_t sb = smem_base + (uint32_t)(c % NSTAGE) * STAGE_BYTES;
        #pragma unroll
        for (int i = 0; i < 2; ++i) {               // fp16 Ah: 512 chunks
            const int idx = tid + i * 256;
            const int row = idx >> 2, c16 = idx & 3;
            CP_ASYNC16(sb + SM_AH + row * 80 + c16 * 16,
                       Ah + (size_t)(m0 + row) * KEL + koff + c16 * 8);
        }
        {                                           // fp16 Bh: 256 chunks
            const int row = tid >> 2, c16 = tid & 3;
            CP_ASYNC16(sb + SM_BH + row * 80 + c16 * 16,
                       Bh + (size_t)(n0 + row) * KEL + koff + c16 * 8);
        }
        {                                           // fp8 A8 + Al8: 256 each
            const int row = tid >> 1, c16 = tid & 1;
            const size_t ga = (size_t)(m0 + row) * KEL + koff + c16 * 16;
            CP_ASYNC16(sb + SM_A8 + row * 48 + c16 * 16, A8 + ga);
            CP_ASYNC16(sb + SM_AL8 + row * 48 + c16 * 16, Al8 + ga);
        }
        {                                           // fp8 B8 / Bl8: 128 each
            const int t = tid & 127;
            const int row = t >> 1, c16 = t & 1;
            const size_t gb = (size_t)(n0 + row) * KEL + koff + c16 * 16;
            if (tid < 128)
                CP_ASYNC16(sb + SM_B8 + row * 48 + c16 * 16, B8 + gb);
            else
                CP_ASYNC16(sb + SM_BL8 + row * 48 + c16 * 16, Bl8 + gb);
        }
        CP_COMMIT();
    };

    load_chunk(0);
    load_chunk(1);

    // fp16 ldmatrix lane addressing (proven rounds 4-8)
    const int rowA = wm * 32 + (lid & 15);
    const int rowB = wn * 32 + (lid & 15);
    const uint32_t kb = (uint32_t)((lid >> 4) * 16);

    // fp8 ldmatrix lane addressing (x4 over k32 via b16 byte-pair view; verified R9)
    const int g = lid >> 3;
    const uint32_t a8_lane = (uint32_t)((((g & 1) * 8) + (lid & 7)) * 48 + (g >> 1) * 16);
    const uint32_t b8_lane = (uint32_t)((((g >> 1) * 8) + (lid & 7)) * 48 + (g & 1) * 16);

    #pragma unroll 1
    for (int c = 0; c < NC; ++c) {
        if (c + 1 < NC) { CP_WAIT(1); } else { CP_WAIT(0); }
        __syncthreads();
        if (c + 2 < NC) load_chunk(c + 2);

        const uint32_t sb = smem_base + (uint32_t)(c % NSTAGE) * STAGE_BYTES;

        // ---- fp16 hi phase: 16 HMMA ----
        #pragma unroll
        for (int ks = 0; ks < 2; ++ks) {
            const uint32_t kbyte = (uint32_t)(ks * 32) + kb;
            uint32_t ah[2][4];
            #pragma unroll
            for (int mt = 0; mt < 2; ++mt)
                LDSM4(ah[mt], sb + SM_AH + (uint32_t)((rowA + mt * 16) * 80) + kbyte);
            uint32_t bh[4][2];
            #pragma unroll
            for (int np = 0; np < 2; ++np) {
                uint32_t t4[4];
                LDSM4(t4, sb + SM_BH + (uint32_t)((rowB + np * 16) * 80) + kbyte);
                bh[2 * np][0] = t4[0]; bh[2 * np][1] = t4[2];
                bh[2 * np + 1][0] = t4[1]; bh[2 * np + 1][1] = t4[3];
            }
            #pragma unroll
            for (int mt = 0; mt < 2; ++mt)
                #pragma unroll
                for (int nt = 0; nt < 4; ++nt)
                    MMA16816(acc_hi[mt][nt], ah[mt], bh[nt]);
        }

        // ---- fp8 lo phase: 16 QMMA (k32 each) ----
        {
            uint32_t a8h[2][4], a8l[2][4];
            #pragma unroll
            for (int mt = 0; mt < 2; ++mt) {
                const uint32_t base = (uint32_t)((wm * 32 + mt * 16) * 48) + a8_lane;
                LDSM4(a8h[mt], sb + SM_A8 + base);
                LDSM4(a8l[mt], sb + SM_AL8 + base);
            }
            uint32_t b8h[4][2], b8l[4][2];
            #pragma unroll
            for (int np = 0; np < 2; ++np) {
                const uint32_t base = (uint32_t)((wn * 32 + np * 16) * 48) + b8_lane;
                uint32_t t4[4];
                LDSM4(t4, sb + SM_B8 + base);
                b8h[2 * np][0] = t4[0]; b8h[2 * np][1] = t4[1];
                b8h[2 * np + 1][0] = t4[2]; b8h[2 * np + 1][1] = t4[3];
                LDSM4(t4, sb + SM_BL8 + base);
                b8l[2 * np][0] = t4[0]; b8l[2 * np][1] = t4[1];
                b8l[2 * np + 1][0] = t4[2]; b8l[2 * np + 1][1] = t4[3];
            }
            #pragma unroll
            for (int mt = 0; mt < 2; ++mt)
                #pragma unroll
                for (int nt = 0; nt < 4; ++nt)
                    MMAF8(acc_lo[mt][nt], a8h[mt], b8l[nt]);
            #pragma unroll
            for (int mt = 0; mt < 2; ++mt)
                #pragma unroll
                for (int nt = 0; nt < 4; ++nt)
                    MMAF8(acc_lo[mt][nt], a8l[mt], b8h[nt]);
        }
    }

    // ---- epilogue ----
    const int gq = lid >> 2, t4i = lid & 3;
    #pragma unroll
    for (int mt = 0; mt < 2; ++mt) {
        const int m = m0 + wm * 32 + mt * 16 + gq;
        float bm0 = 0.f, bm8 = 0.f;
        if (MODE == 1) { bm0 = bias[m]; bm8 = bias[m + 8]; }
        #pragma unroll
        for (int nt = 0; nt < 4; ++nt) {
            const int n = n0 + wn * 32 + nt * 8 + 2 * t4i;
            float v0 = acc_hi[mt][nt][0] + acc_lo[mt][nt][0] * INV_RSCALE;
            float v1 = acc_hi[mt][nt][1] + acc_lo[mt][nt][1] * INV_RSCALE;
            float v2 = acc_hi[mt][nt][2] + acc_lo[mt][nt][2] * INV_RSCALE;
            float v3 = acc_hi[mt][nt][3] + acc_lo[mt][nt][3] * INV_RSCALE;
            if (MODE == 0) {
                const float bn0 = bias[n], bn1 = bias[n + 1];
                v0 += bn0; v1 += bn1; v2 += bn0; v3 += bn1;
            } else if (MODE == 1) {
                v0 += bm0; v1 += bm0; v2 += bm8; v3 += bm8;
            } else if (MODE == 2) {
                v0 *= 0.03125f; v1 *= 0.03125f; v2 *= 0.03125f; v3 *= 0.03125f;
            }
            if (MODE == 0 || MODE == 1) {
                __half h0, h1; uint8_t f0, f1, l0, l1;
                const size_t o0 = (size_t)b * sO + (size_t)m * ldo + n;
                split3(v0, h0, f0, l0); split3(v1, h1, f1, l1);
                { __half2 hh; hh.x = h0; hh.y = h1;
                  *(__half2*)(outH + o0) = hh;
                  uchar2 u8; u8.x = f0; u8.y = f1; *(uchar2*)(out8 + o0) = u8;
                  uchar2 ul; ul.x = l0; ul.y = l1; *(uchar2*)(outL8 + o0) = ul; }
                const size_t o8 = (size_t)b * sO + (size_t)(m + 8) * ldo + n;
                split3(v2, h0, f0, l0); split3(v3, h1, f1, l1);
                { __half2 hh; hh.x = h0; hh.y = h1;
                  *(__half2*)(outH + o8) = hh;
                  uchar2 u8; u8.x = f0; u8.y = f1; *(uchar2*)(out8 + o8) = u8;
                  uchar2 ul; ul.x = l0; ul.y = l1; *(uchar2*)(outL8 + o8) = ul; }
            } else {
                float2 f0; f0.x = v0; f0.y = v1;
                float2 f8; f8.x = v2; f8.y = v3;
                *(float2*)(outF + (size_t)b * sO + (size_t)m * ldo + n) = f0;
                *(float2*)(outF + (size_t)b * sO + (size_t)(m + 8) * ldo + n) = f8;
            }
        }
    }
}

// ---------------------------------------------------------------------------
// fp32 -> {fp16, e4m3, e4m3-residual} for all three weight matrices
// ---------------------------------------------------------------------------
__global__ __launch_bounds__(256) void wsplit3_kernel(
    const float* __restrict__ w0, const float* __restrict__ w1,
    const float* __restrict__ w2,
    __half* __restrict__ h0, uint8_t* __restrict__ f0, uint8_t* __restrict__ l0,
    __half* __restrict__ h1, uint8_t* __restrict__ f1, uint8_t* __restrict__ l1,
    __half* __restrict__ h2, uint8_t* __restrict__ f2, uint8_t* __restrict__ l2)
{
    const int which = blockIdx.y;
    const float* w = (which == 0) ? w0 : (which == 1) ? w1 : w2;
    __half* h = (which == 0) ? h0 : (which == 1) ? h1 : h2;
    uint8_t* f = (which == 0) ? f0 : (which == 1) ? f1 : f2;
    uint8_t* l = (which == 0) ? l0 : (which == 1) ? l1 : l2;
    const int n = D_ * D_;
    for (int i = blockIdx.x * 256 + threadIdx.x; i < n; i += gridDim.x * 256) {
        __half hi; uint8_t v8, vl8;
        split3(w[i], hi, v8, vl8);
        h[i] = hi; f[i] = v8; l[i] = vl8;
    }
}

// ---------------------------------------------------------------------------
// x[b,d,s] -> xT[b,s,d] with 3-form split
// ---------------------------------------------------------------------------
__global__ __launch_bounds__(256) void xpose_split_kernel(const float* __restrict__ x)
{
    __shared__ float t[32][33];
    const int b = blockIdx.z;
    const int d0 = blockIdx.y * 32;
    const int s0 = blockIdx.x * 32;
    const int tx = threadIdx.x & 31;
    const int ty = threadIdx.x >> 5;   // 0..7
    const float* X = x + (size_t)b * D_ * S_;

    #pragma unroll
    for (int i = 0; i < 4; ++i)
        t[ty + i * 8][tx] = X[(size_t)(d0 + ty + i * 8) * S_ + s0 + tx];
    __syncthreads();
    #pragma unroll
    for (int i = 0; i < 4; ++i) {
        const int s = s0 + ty + i * 8;
        const int d = d0 + tx;
        const float v = t[tx][ty + i * 8];
        __half hi; uint8_t v8, vl8;
        split3(v, hi, v8, vl8);
        const size_t idx = (size_t)b * S_ * D_ + (size_t)s * D_ + d;
        g_xTh[idx] = hi;
        g_xT8[idx] = v8;
        g_xTl8[idx] = vl8;
    }
}

// ---------------------------------------------------------------------------
// softmax over rows of g_S, output P in 3-form split
// ---------------------------------------------------------------------------
__global__ __launch_bounds__(256) void softmax_split_kernel()
{
    const size_t row = blockIdx.x;  // 0 .. B_*S_-1
    const float* __restrict__ p = g_S + row * S_;
    __half* __restrict__ ph = g_Ph + row * S_;
    uint8_t* __restrict__ p8 = g_P8 + row * S_;
    uint8_t* __restrict__ pl8 = g_Pl8 + row * S_;
    const int tid = threadIdx.x;

    float v[8];
    #pragma unroll
    for (int i = 0; i < 8; ++i) v[i] = p[i * 256 + tid];

    float m = v[0];
    #pragma unroll
    for (int i = 1; i < 8; ++i) m = fmaxf(m, v[i]);

    __shared__ float red[8];
    #pragma unroll
    for (int o = 16; o > 0; o >>= 1)
        m = fmaxf(m, __shfl_xor_sync(0xffffffffu, m, o));
    if ((tid & 31) == 0) red[tid >> 5] = m;
    __syncthreads();
    m = red[0];
    #pragma unroll
    for (int i = 1; i < 8; ++i) m = fmaxf(m, red[i]);
    __syncthreads();

    float s = 0.f;
    #pragma unroll
    for (int i = 0; i < 8; ++i) { v[i] = expf(v[i] - m); s += v[i]; }
    #pragma unroll
    for (int o = 16; o > 0; o >>= 1)
        s += __shfl_xor_sync(0xffffffffu, s, o);
    if ((tid & 31) == 0) red[tid >> 5] = s;
    __syncthreads();
    s = 0.f;
    #pragma unroll
    for (int i = 0; i < 8; ++i) s += red[i];

    const float inv = 1.0f / s;
    #pragma unroll
    for (int i = 0; i < 8; ++i) {
        __half hi; uint8_t v8, vl8;
        split3(v[i] * inv, hi, v8, vl8);
        ph[i * 256 + tid] = hi;
        p8[i * 256 + tid] = v8;
        pl8[i * 256 + tid] = vl8;
    }
}

// ---------------------------------------------------------------------------
extern "C" void kernel_launch(void* const* d_in, const int* in_sizes, int n_in,
                              void* d_out, int out_size)
{
    const float* x  = (const float*)d_in[0];
    const float* Wq = (const float*)d_in[1];
    const float* bq = (const float*)d_in[2];
    const float* Wk = (const float*)d_in[3];
    const float* bk = (const float*)d_in[4];
    const float* Wv = (const float*)d_in[5];
    const float* bv = (const float*)d_in[6];
    float* out = (float*)d_out;

    const int SMEM_SZ = NSTAGE * STAGE_BYTES;   // 101376

    cudaFuncSetAttribute(tc_gemm<1024, 0>, cudaFuncAttributeMaxDynamicSharedMemorySize, SMEM_SZ);
    cudaFuncSetAttribute(tc_gemm<1024, 1>, cudaFuncAttributeMaxDynamicSharedMemorySize, SMEM_SZ);
    cudaFuncSetAttribute(tc_gemm<1024, 2>, cudaFuncAttributeMaxDynamicSharedMemorySize, SMEM_SZ);
    cudaFuncSetAttribute(tc_gemm<2048, 3>, cudaFuncAttributeMaxDynamicSharedMemorySize, SMEM_SZ);

    __half *xTh, *Wqh, *Wkh, *Wvh, *Qh, *Kh, *Vh, *Ph;
    uint8_t *xT8, *xTl8, *Wq8, *Wql8, *Wk8, *Wkl8, *Wv8, *Wvl8;
    uint8_t *Q8, *Ql8, *K8, *Kl8, *V8, *Vl8, *P8, *Pl8;
    float* Sc;
    cudaGetSymbolAddress((void**)&xTh, g_xTh);
    cudaGetSymbolAddress((void**)&xT8, g_xT8);
    cudaGetSymbolAddress((void**)&xTl8, g_xTl8);
    cudaGetSymbolAddress((void**)&Wqh, g_Wqh);
    cudaGetSymbolAddress((void**)&Wq8, g_Wq8);
    cudaGetSymbolAddress((void**)&Wql8, g_Wql8);
    cudaGetSymbolAddress((void**)&Wkh, g_Wkh);
    cudaGetSymbolAddress((void**)&Wk8, g_Wk8);
    cudaGetSymbolAddress((void**)&Wkl8, g_Wkl8);
    cudaGetSymbolAddress((void**)&Wvh, g_Wvh);
    cudaGetSymbolAddress((void**)&Wv8, g_Wv8);
    cudaGetSymbolAddress((void**)&Wvl8, g_Wvl8);
    cudaGetSymbolAddress((void**)&Qh, g_Qh);
    cudaGetSymbolAddress((void**)&Q8, g_Q8);
    cudaGetSymbolAddress((void**)&Ql8, g_Ql8);
    cudaGetSymbolAddress((void**)&Kh, g_Kh);
    cudaGetSymbolAddress((void**)&K8, g_K8);
    cudaGetSymbolAddress((void**)&Kl8, g_Kl8);
    cudaGetSymbolAddress((void**)&Vh, g_Vh);
    cudaGetSymbolAddress((void**)&V8, g_V8);
    cudaGetSymbolAddress((void**)&Vl8, g_Vl8);
    cudaGetSymbolAddress((void**)&Ph, g_Ph);
    cudaGetSymbolAddress((void**)&P8, g_P8);
    cudaGetSymbolAddress((void**)&Pl8, g_Pl8);
    cudaGetSymbolAddress((void**)&Sc, g_S);

    const size_t SD = (size_t)S_ * D_;
    const size_t SS = (size_t)S_ * S_;

    // 1) operand preparation
    wsplit3_kernel<<<dim3(64, 3), 256>>>(Wq, Wk, Wv,
                                         Wqh, Wq8, Wql8,
                                         Wkh, Wk8, Wkl8,
                                         Wvh, Wv8, Wvl8);
    xpose_split_kernel<<<dim3(S_ / 32, D_ / 32, B_), 256>>>(x);

    // 2) projections
    // Q[s,e] = xT[s,:].W_q[e,:] + bq[e]
    tc_gemm<1024, 0><<<dim3(D_ / 64, S_ / 128, B_), 256, SMEM_SZ>>>(
        xTh, xT8, xTl8, SD, Wqh, Wq8, Wql8, 0, bq,
        nullptr, Qh, Q8, Ql8, SD, D_);
    tc_gemm<1024, 0><<<dim3(D_ / 64, S_ / 128, B_), 256, SMEM_SZ>>>(
        xTh, xT8, xTl8, SD, Wkh, Wk8, Wkl8, 0, bk,
        nullptr, Kh, K8, Kl8, SD, D_);
    // V[e,t] = W_v[e,:].xT[t,:] + bv[e]
    tc_gemm<1024, 1><<<dim3(S_ / 64, D_ / 128, B_), 256, SMEM_SZ>>>(
        Wvh, Wv8, Wvl8, 0, xTh, xT8, xTl8, SD, bv,
        nullptr, Vh, V8, Vl8, SD, S_);

    // 3) scores S[s,t] = Q[s,:].K[t,:] / 32
    tc_gemm<1024, 2><<<dim3(S_ / 64, S_ / 128, B_), 256, SMEM_SZ>>>(
        Qh, Q8, Ql8, SD, Kh, K8, Kl8, SD, nullptr,
        Sc, nullptr, nullptr, nullptr, SS, S_);

    // 4) softmax rows -> P 3-form
    softmax_split_kernel<<<B_ * S_, 256>>>();

    // 5) out[s,e] = P[s,:].V[e,:]
    tc_gemm<2048, 3><<<dim3(D_ / 64, S_ / 128, B_), 256, SMEM_SZ>>>(
        Ph, P8, Pl8, SS, Vh, V8, Vl8, SD, nullptr,
        out, nullptr, nullptr, nullptr, SD, D_);
}